// round 1
// baseline (speedup 1.0000x reference)
#include <cuda_runtime.h>
#include <cstdint>

#define B_   2
#define T_   2048
#define C_   1024
#define H_   16
#define HD_  64
#define BT_  (B_ * T_)       // 4096
#define NQKV (3 * C_)        // 3072

// Scratch (no cudaMalloc allowed): Q/K/V head-major [B*H, T, HD], attn out [B*T, C]
__device__ float g_q[B_ * H_ * T_ * HD_];
__device__ float g_k[B_ * H_ * T_ * HD_];
__device__ float g_v[B_ * H_ * T_ * HD_];
__device__ float g_att[(size_t)BT_ * C_];

// ---------------------------------------------------------------------------
// SGEMM: C[M,N] = A[M,K] * Bw[N,K]^T + bias[N]
// MODE 0: scatter into g_q/g_k/g_v head-major (QKV projection)
// MODE 1: plain row-major store into Cout (output projection)
// Tiles: BM=BN=128, BK=8; 256 threads; 8x8 per thread (split-4 fragments).
// ---------------------------------------------------------------------------
#define BM 128
#define BN 128
#define BK 8

template <int MODE>
__global__ __launch_bounds__(256) void sgemm_kernel(
    const float* __restrict__ A, const float* __restrict__ Bw,
    const float* __restrict__ bias, float* __restrict__ Cout,
    float* __restrict__ qb, float* __restrict__ kb, float* __restrict__ vb,
    int M, int N, int K)
{
    __shared__ float As[BK][BM + 4];   // +4 pad: conflict-light transposed stores
    __shared__ float Bs[BK][BN + 4];

    const int tid = threadIdx.x;
    const int tx = tid & 15;          // 0..15 (N dir)
    const int ty = tid >> 4;          // 0..15 (M dir)
    const int bm = blockIdx.y * BM;
    const int bn = blockIdx.x * BN;

    const int lr = tid >> 1;          // 0..127
    const int lc = (tid & 1) * 4;     // 0 or 4
    const float* Ag = A  + (size_t)(bm + lr) * K + lc;
    const float* Bg = Bw + (size_t)(bn + lr) * K + lc;

    float acc[8][8];
    #pragma unroll
    for (int i = 0; i < 8; i++)
        #pragma unroll
        for (int j = 0; j < 8; j++) acc[i][j] = 0.0f;

    for (int k0 = 0; k0 < K; k0 += BK) {
        float4 av = *(const float4*)(Ag + k0);
        float4 bv = *(const float4*)(Bg + k0);
        As[lc + 0][lr] = av.x; As[lc + 1][lr] = av.y;
        As[lc + 2][lr] = av.z; As[lc + 3][lr] = av.w;
        Bs[lc + 0][lr] = bv.x; Bs[lc + 1][lr] = bv.y;
        Bs[lc + 2][lr] = bv.z; Bs[lc + 3][lr] = bv.w;
        __syncthreads();

        #pragma unroll
        for (int k = 0; k < BK; k++) {
            float a[8], b[8];
            *(float4*)&a[0] = *(const float4*)&As[k][ty * 4];
            *(float4*)&a[4] = *(const float4*)&As[k][64 + ty * 4];
            *(float4*)&b[0] = *(const float4*)&Bs[k][tx * 4];
            *(float4*)&b[4] = *(const float4*)&Bs[k][64 + tx * 4];
            #pragma unroll
            for (int i = 0; i < 8; i++)
                #pragma unroll
                for (int j = 0; j < 8; j++)
                    acc[i][j] += a[i] * b[j];
        }
        __syncthreads();
    }

    #pragma unroll
    for (int i = 0; i < 8; i++) {
        const int ri  = (i < 4) ? (ty * 4 + i) : (64 + ty * 4 + i - 4);
        const int row = bm + ri;
        #pragma unroll
        for (int j = 0; j < 8; j++) {
            const int cj  = (j < 4) ? (tx * 4 + j) : (64 + tx * 4 + j - 4);
            const int col = bn + cj;
            const float v = acc[i][j] + bias[col];
            if (MODE == 0) {
                const int b    = row >> 11;          // / T_
                const int t    = row & (T_ - 1);
                const int part = col >> 10;          // / C_
                const int c    = col & (C_ - 1);
                const int h    = c >> 6;
                const int d    = c & 63;
                const size_t idx = ((size_t)((b * H_ + h) * T_ + t)) * HD_ + d;
                float* dst = (part == 0) ? qb : (part == 1) ? kb : vb;
                dst[idx] = v;
            } else {
                Cout[(size_t)row * N + col] = v;
            }
        }
    }
}

// ---------------------------------------------------------------------------
// Flash-style causal attention, fp32.
// Block: 256 threads (16x16), 64-query tile per block, HD=64, 64-key tiles.
// grid = (T/64, B*H).
// ---------------------------------------------------------------------------
#define ATTN_SMEM_FLOATS (64 * 65 * 3 + 64 * 68)
#define ATTN_SMEM_BYTES  (ATTN_SMEM_FLOATS * 4)

__device__ __forceinline__ float redmax16(float v) {
    v = fmaxf(v, __shfl_xor_sync(0xffffffffu, v, 8));
    v = fmaxf(v, __shfl_xor_sync(0xffffffffu, v, 4));
    v = fmaxf(v, __shfl_xor_sync(0xffffffffu, v, 2));
    v = fmaxf(v, __shfl_xor_sync(0xffffffffu, v, 1));
    return v;
}
__device__ __forceinline__ float redsum16(float v) {
    v += __shfl_xor_sync(0xffffffffu, v, 8);
    v += __shfl_xor_sync(0xffffffffu, v, 4);
    v += __shfl_xor_sync(0xffffffffu, v, 2);
    v += __shfl_xor_sync(0xffffffffu, v, 1);
    return v;
}

__global__ __launch_bounds__(256) void attn_kernel(
    const float* __restrict__ Q, const float* __restrict__ K,
    const float* __restrict__ V, float* __restrict__ Oatt)
{
    extern __shared__ float sm[];
    float* Qt = sm;                   // [64][65], transposed: Qt[d][row]
    float* Kt = Qt + 64 * 65;         // [64][65], transposed: Kt[d][col]
    float* Vs = Kt + 64 * 65;         // [64][68], row-major: Vs[col][d]
    float* Pt = Vs + 64 * 68;         // [64][65], transposed: Pt[col][row]

    const int tid = threadIdx.x;
    const int tx  = tid & 15;
    const int ty  = tid >> 4;
    const int qt  = blockIdx.x;
    const int bh  = blockIdx.y;
    const int q0  = qt * 64;

    const float* Qg = Q + (size_t)bh * T_ * HD_;
    const float* Kg = K + (size_t)bh * T_ * HD_;
    const float* Vg = V + (size_t)bh * T_ * HD_;

    const int lrr = tid >> 4;          // 0..15
    const int lc4 = (tid & 15) * 4;    // 0..60

    // Load Q tile transposed (made visible by first in-loop __syncthreads)
    #pragma unroll
    for (int s = 0; s < 4; s++) {
        const int r = lrr + s * 16;
        float4 qv = *(const float4*)(Qg + (size_t)(q0 + r) * HD_ + lc4);
        Qt[(lc4 + 0) * 65 + r] = qv.x;
        Qt[(lc4 + 1) * 65 + r] = qv.y;
        Qt[(lc4 + 2) * 65 + r] = qv.z;
        Qt[(lc4 + 3) * 65 + r] = qv.w;
    }

    float m_i[4], l_i[4], o[4][4];
    #pragma unroll
    for (int i = 0; i < 4; i++) {
        m_i[i] = -1e30f;
        l_i[i] = 0.0f;
        #pragma unroll
        for (int j = 0; j < 4; j++) o[i][j] = 0.0f;
    }

    for (int kt = 0; kt <= qt; kt++) {
        const int k0 = kt * 64;

        // load K (transposed) + V tiles
        #pragma unroll
        for (int s = 0; s < 4; s++) {
            const int r = lrr + s * 16;
            float4 kv = *(const float4*)(Kg + (size_t)(k0 + r) * HD_ + lc4);
            Kt[(lc4 + 0) * 65 + r] = kv.x;
            Kt[(lc4 + 1) * 65 + r] = kv.y;
            Kt[(lc4 + 2) * 65 + r] = kv.z;
            Kt[(lc4 + 3) * 65 + r] = kv.w;
            float4 vv = *(const float4*)(Vg + (size_t)(k0 + r) * HD_ + lc4);
            *(float4*)&Vs[r * 68 + lc4] = vv;
        }
        __syncthreads();   // (A) tiles visible (also covers Qt on first iter)

        // S = Q * K^T for this 64x64 tile; each thread 4x4
        float s4[4][4];
        #pragma unroll
        for (int i = 0; i < 4; i++)
            #pragma unroll
            for (int j = 0; j < 4; j++) s4[i][j] = 0.0f;

        #pragma unroll 8
        for (int d = 0; d < 64; d++) {
            float qv[4], kv[4];
            #pragma unroll
            for (int i = 0; i < 4; i++) qv[i] = Qt[d * 65 + 4 * ty + i];
            #pragma unroll
            for (int j = 0; j < 4; j++) kv[j] = Kt[d * 65 + 4 * tx + j];
            #pragma unroll
            for (int i = 0; i < 4; i++)
                #pragma unroll
                for (int j = 0; j < 4; j++)
                    s4[i][j] += qv[i] * kv[j];
        }

        // scale + causal mask (only diagonal tile partially masked)
        #pragma unroll
        for (int i = 0; i < 4; i++)
            #pragma unroll
            for (int j = 0; j < 4; j++) s4[i][j] *= 0.125f;  // 1/sqrt(64)
        if (kt == qt) {
            #pragma unroll
            for (int i = 0; i < 4; i++)
                #pragma unroll
                for (int j = 0; j < 4; j++)
                    if (k0 + 4 * tx + j > q0 + 4 * ty + i) s4[i][j] = -1e30f;
        }

        // online softmax update + write P transposed
        #pragma unroll
        for (int i = 0; i < 4; i++) {
            float rm = fmaxf(fmaxf(s4[i][0], s4[i][1]), fmaxf(s4[i][2], s4[i][3]));
            rm = redmax16(rm);
            const float mn    = fmaxf(m_i[i], rm);
            const float alpha = __expf(m_i[i] - mn);
            float rs = 0.0f;
            #pragma unroll
            for (int j = 0; j < 4; j++) {
                const float p = __expf(s4[i][j] - mn);
                s4[i][j] = p;
                rs += p;
            }
            rs = redsum16(rs);
            l_i[i] = l_i[i] * alpha + rs;
            m_i[i] = mn;
            #pragma unroll
            for (int j = 0; j < 4; j++) o[i][j] *= alpha;
            #pragma unroll
            for (int j = 0; j < 4; j++)
                Pt[(4 * tx + j) * 65 + 4 * ty + i] = s4[i][j];
        }
        __syncthreads();   // (B) Pt visible

        // O += P * V
        #pragma unroll 8
        for (int c = 0; c < 64; c++) {
            float pv[4], vv[4];
            #pragma unroll
            for (int i = 0; i < 4; i++) pv[i] = Pt[c * 65 + 4 * ty + i];
            *(float4*)&vv[0] = *(const float4*)&Vs[c * 68 + 4 * tx];
            #pragma unroll
            for (int i = 0; i < 4; i++)
                #pragma unroll
                for (int j = 0; j < 4; j++)
                    o[i][j] += pv[i] * vv[j];
        }
        __syncthreads();   // (C) done with Pt/Vs before next-iter overwrite
    }

    // normalize + write to [B*T, C] layout for the output projection
    const int b = bh >> 4;
    const int h = bh & 15;
    #pragma unroll
    for (int i = 0; i < 4; i++) {
        const int t = q0 + 4 * ty + i;
        const float inv = 1.0f / l_i[i];
        float4 r;
        r.x = o[i][0] * inv; r.y = o[i][1] * inv;
        r.z = o[i][2] * inv; r.w = o[i][3] * inv;
        *(float4*)&Oatt[((size_t)(b * T_ + t)) * C_ + h * 64 + 4 * tx] = r;
    }
}

// ---------------------------------------------------------------------------
extern "C" void kernel_launch(void* const* d_in, const int* in_sizes, int n_in,
                              void* d_out, int out_size)
{
    const float* x     = (const float*)d_in[0];
    // d_in[1] = mask (causal, known statically; unused)
    const float* qkv_w = (const float*)d_in[2];
    const float* qkv_b = (const float*)d_in[3];
    const float* out_w = (const float*)d_in[4];
    const float* out_b = (const float*)d_in[5];
    float* out = (float*)d_out;

    float *qp, *kp, *vp, *ap;
    cudaGetSymbolAddress((void**)&qp, g_q);
    cudaGetSymbolAddress((void**)&kp, g_k);
    cudaGetSymbolAddress((void**)&vp, g_v);
    cudaGetSymbolAddress((void**)&ap, g_att);

    cudaFuncSetAttribute(attn_kernel,
                         cudaFuncAttributeMaxDynamicSharedMemorySize,
                         ATTN_SMEM_BYTES);

    // 1) QKV projection: [4096,1024] x [3072,1024]^T -> head-major Q/K/V
    dim3 g1(NQKV / BN, BT_ / BM);
    sgemm_kernel<0><<<g1, 256>>>(x, qkv_w, qkv_b, nullptr, qp, kp, vp,
                                 BT_, NQKV, C_);

    // 2) causal flash attention
    dim3 g2(T_ / 64, B_ * H_);
    attn_kernel<<<g2, 256, ATTN_SMEM_BYTES>>>(qp, kp, vp, ap);

    // 3) output projection: [4096,1024] x [1024,1024]^T + bias -> d_out
    dim3 g3(C_ / BN, BT_ / BM);
    sgemm_kernel<1><<<g3, 256>>>(ap, out_w, out_b, out,
                                 nullptr, nullptr, nullptr,
                                 BT_, C_, C_);
}

// round 2
// speedup vs baseline: 5.6224x; 5.6224x over previous
#include <cuda_runtime.h>
#include <cstdint>

#define B_   2
#define T_   2048
#define C_   1024
#define H_   16
#define HD_  64
#define BT_  (B_ * T_)       // 4096
#define NQKV (3 * C_)        // 3072

// Scratch (no cudaMalloc allowed)
__device__ float g_q[B_ * H_ * T_ * HD_];
__device__ float g_k[B_ * H_ * T_ * HD_];
__device__ float g_v[B_ * H_ * T_ * HD_];
__device__ float g_att[(size_t)BT_ * C_];

// ---------------------------------------------------------------------------
__device__ __forceinline__ uint32_t f2tf(float f) {
    uint32_t u;
    asm("cvt.rna.tf32.f32 %0, %1;" : "=r"(u) : "f"(f));
    return u;
}

__device__ __forceinline__ void mma8(float* d,
                                     uint32_t a0, uint32_t a1, uint32_t a2, uint32_t a3,
                                     uint32_t b0, uint32_t b1) {
    asm volatile(
        "mma.sync.aligned.m16n8k8.row.col.f32.tf32.tf32.f32 "
        "{%0,%1,%2,%3}, {%4,%5,%6,%7}, {%8,%9}, {%0,%1,%2,%3};\n"
        : "+f"(d[0]), "+f"(d[1]), "+f"(d[2]), "+f"(d[3])
        : "r"(a0), "r"(a1), "r"(a2), "r"(a3), "r"(b0), "r"(b1));
}

// ---------------------------------------------------------------------------
// TF32 GEMM: C[M,N] = A[M,K] * Bw[N,K]^T + bias
// MODE 0: scatter to head-major q/k/v (q scaled by 0.125)
// MODE 1: row-major store to Cout
// 256 threads, BM=BN=128, BK=32; warp tile 64x32 (2x4 warp grid).
// ---------------------------------------------------------------------------
#define GLDA 36   // smem row stride (floats): bank = 4*row + col (conflict-free frags)

template <int MODE>
__global__ __launch_bounds__(256) void gemm_tf32(
    const float* __restrict__ A, const float* __restrict__ Bw,
    const float* __restrict__ bias, float* __restrict__ Cout,
    float* __restrict__ qb, float* __restrict__ kb, float* __restrict__ vb,
    int M, int N, int K)
{
    __shared__ uint32_t As[128 * GLDA];
    __shared__ uint32_t Bs[128 * GLDA];

    const int tid  = threadIdx.x;
    const int lane = tid & 31;
    const int warp = tid >> 5;
    const int g    = lane >> 2;      // groupID 0..7
    const int tg   = lane & 3;       // threadID-in-group 0..3
    const int wm   = warp >> 2;      // 0..1
    const int wn   = warp & 3;       // 0..3
    const int bm   = blockIdx.y * 128;
    const int bn   = blockIdx.x * 128;

    const int lrow = tid >> 3;       // 0..31
    const int lq   = tid & 7;        // float4 col 0..7

    float acc[4][4][4];
    #pragma unroll
    for (int mi = 0; mi < 4; mi++)
        #pragma unroll
        for (int ni = 0; ni < 4; ni++)
            #pragma unroll
            for (int j = 0; j < 4; j++) acc[mi][ni][j] = 0.0f;

    for (int k0 = 0; k0 < K; k0 += 32) {
        #pragma unroll
        for (int s = 0; s < 4; s++) {
            const int r = lrow + 32 * s;
            float4 av = *(const float4*)(A  + (size_t)(bm + r) * K + k0 + lq * 4);
            float4 bv = *(const float4*)(Bw + (size_t)(bn + r) * K + k0 + lq * 4);
            uint4 au = make_uint4(f2tf(av.x), f2tf(av.y), f2tf(av.z), f2tf(av.w));
            uint4 bu = make_uint4(f2tf(bv.x), f2tf(bv.y), f2tf(bv.z), f2tf(bv.w));
            *(uint4*)&As[r * GLDA + lq * 4] = au;
            *(uint4*)&Bs[r * GLDA + lq * 4] = bu;
        }
        __syncthreads();

        #pragma unroll
        for (int kk = 0; kk < 4; kk++) {
            uint32_t af[4][4], bf[4][2];
            #pragma unroll
            for (int mi = 0; mi < 4; mi++) {
                const int r = wm * 64 + mi * 16;
                af[mi][0] = As[(r + g) * GLDA + kk * 8 + tg];
                af[mi][1] = As[(r + g + 8) * GLDA + kk * 8 + tg];
                af[mi][2] = As[(r + g) * GLDA + kk * 8 + tg + 4];
                af[mi][3] = As[(r + g + 8) * GLDA + kk * 8 + tg + 4];
            }
            #pragma unroll
            for (int ni = 0; ni < 4; ni++) {
                const int c = wn * 32 + ni * 8;
                bf[ni][0] = Bs[(c + g) * GLDA + kk * 8 + tg];
                bf[ni][1] = Bs[(c + g) * GLDA + kk * 8 + tg + 4];
            }
            #pragma unroll
            for (int mi = 0; mi < 4; mi++)
                #pragma unroll
                for (int ni = 0; ni < 4; ni++)
                    mma8(acc[mi][ni], af[mi][0], af[mi][1], af[mi][2], af[mi][3],
                         bf[ni][0], bf[ni][1]);
        }
        __syncthreads();
    }

    // epilogue
    #pragma unroll
    for (int mi = 0; mi < 4; mi++) {
        const int r0 = bm + wm * 64 + mi * 16 + g;
        const int r1 = r0 + 8;
        #pragma unroll
        for (int ni = 0; ni < 4; ni++) {
            const int col = bn + wn * 32 + ni * 8 + 2 * tg;
            const float b0 = bias[col], b1 = bias[col + 1];
            float v00 = acc[mi][ni][0] + b0, v01 = acc[mi][ni][1] + b1;
            float v10 = acc[mi][ni][2] + b0, v11 = acc[mi][ni][3] + b1;
            if (MODE == 0) {
                const int part = col >> 10;
                const int c    = col & (C_ - 1);
                const int h    = c >> 6;
                const int d    = c & 63;
                if (part == 0) { v00 *= 0.125f; v01 *= 0.125f; v10 *= 0.125f; v11 *= 0.125f; }
                float* dst = (part == 0) ? qb : (part == 1) ? kb : vb;
                {
                    const int b = r0 >> 11, t = r0 & (T_ - 1);
                    float2 p = make_float2(v00, v01);
                    *(float2*)&dst[((size_t)((b * H_ + h) * T_ + t)) * HD_ + d] = p;
                }
                {
                    const int b = r1 >> 11, t = r1 & (T_ - 1);
                    float2 p = make_float2(v10, v11);
                    *(float2*)&dst[((size_t)((b * H_ + h) * T_ + t)) * HD_ + d] = p;
                }
            } else {
                *(float2*)&Cout[(size_t)r0 * N + col] = make_float2(v00, v01);
                *(float2*)&Cout[(size_t)r1 * N + col] = make_float2(v10, v11);
            }
        }
    }
}

// ---------------------------------------------------------------------------
// TF32 flash attention, causal. 128 threads (4 warps), 64-q tile, 64-k tiles.
// Q pre-scaled by 1/sqrt(HD) in QKV epilogue.
// smem (uint32 words): Qs[64][68], Ks[64][68], Vs[64][72], Ps[64][68]
// ---------------------------------------------------------------------------
#define LQ 68
#define LV 72
#define ATTN_WORDS (64 * LQ * 3 + 64 * LV)
#define ATTN_BYTES (ATTN_WORDS * 4)

__device__ __forceinline__ float red4max(float v) {
    v = fmaxf(v, __shfl_xor_sync(0xffffffffu, v, 1));
    v = fmaxf(v, __shfl_xor_sync(0xffffffffu, v, 2));
    return v;
}
__device__ __forceinline__ float red4sum(float v) {
    v += __shfl_xor_sync(0xffffffffu, v, 1);
    v += __shfl_xor_sync(0xffffffffu, v, 2);
    return v;
}

__global__ __launch_bounds__(128) void attn_tf32(
    const float* __restrict__ Q, const float* __restrict__ K,
    const float* __restrict__ V, float* __restrict__ Oatt)
{
    extern __shared__ uint32_t sm[];
    uint32_t* Qs = sm;
    uint32_t* Ks = Qs + 64 * LQ;
    uint32_t* Vs = Ks + 64 * LQ;
    uint32_t* Ps = Vs + 64 * LV;

    const int tid  = threadIdx.x;
    const int lane = tid & 31;
    const int warp = tid >> 5;          // 0..3
    const int g    = lane >> 2;
    const int tg   = lane & 3;
    const int qt   = blockIdx.x;
    const int bh   = blockIdx.y;
    const int q0   = qt * 64;
    const int rr   = warp * 16;

    const float* Qg = Q + (size_t)bh * T_ * HD_;
    const float* Kg = K + (size_t)bh * T_ * HD_;
    const float* Vg = V + (size_t)bh * T_ * HD_;

    const int r0l = tid >> 4;           // 0..7
    const int q4  = tid & 15;           // float4 col

    // stage Q (already scaled by 0.125)
    #pragma unroll
    for (int s = 0; s < 8; s++) {
        const int r = r0l + 8 * s;
        float4 v = *(const float4*)(Qg + (size_t)(q0 + r) * HD_ + q4 * 4);
        *(uint4*)&Qs[r * LQ + q4 * 4] =
            make_uint4(f2tf(v.x), f2tf(v.y), f2tf(v.z), f2tf(v.w));
    }
    __syncthreads();

    // persistent Q fragments
    uint32_t qf[8][4];
    #pragma unroll
    for (int kk = 0; kk < 8; kk++) {
        qf[kk][0] = Qs[(rr + g) * LQ + kk * 8 + tg];
        qf[kk][1] = Qs[(rr + g + 8) * LQ + kk * 8 + tg];
        qf[kk][2] = Qs[(rr + g) * LQ + kk * 8 + tg + 4];
        qf[kk][3] = Qs[(rr + g + 8) * LQ + kk * 8 + tg + 4];
    }

    float m0 = -1e30f, m1 = -1e30f, l0 = 0.0f, l1 = 0.0f;
    float of[8][4];
    #pragma unroll
    for (int n = 0; n < 8; n++)
        #pragma unroll
        for (int j = 0; j < 4; j++) of[n][j] = 0.0f;

    const int t0 = q0 + rr + g;
    const int t1 = t0 + 8;

    for (int kt = 0; kt <= qt; kt++) {
        const int k0 = kt * 64;
        __syncthreads();   // all warps done reading Ks/Vs from previous iter
        #pragma unroll
        for (int s = 0; s < 8; s++) {
            const int r = r0l + 8 * s;
            float4 kv = *(const float4*)(Kg + (size_t)(k0 + r) * HD_ + q4 * 4);
            float4 vv = *(const float4*)(Vg + (size_t)(k0 + r) * HD_ + q4 * 4);
            *(uint4*)&Ks[r * LQ + q4 * 4] =
                make_uint4(f2tf(kv.x), f2tf(kv.y), f2tf(kv.z), f2tf(kv.w));
            *(uint4*)&Vs[r * LV + q4 * 4] =
                make_uint4(f2tf(vv.x), f2tf(vv.y), f2tf(vv.z), f2tf(vv.w));
        }
        __syncthreads();

        // S = Q * K^T  (B fragment of K^T col-major == K row-major)
        float sf[8][4];
        #pragma unroll
        for (int n = 0; n < 8; n++) {
            sf[n][0] = 0.0f; sf[n][1] = 0.0f; sf[n][2] = 0.0f; sf[n][3] = 0.0f;
            #pragma unroll
            for (int kk = 0; kk < 8; kk++) {
                uint32_t b0 = Ks[(n * 8 + g) * LQ + kk * 8 + tg];
                uint32_t b1 = Ks[(n * 8 + g) * LQ + kk * 8 + tg + 4];
                mma8(sf[n], qf[kk][0], qf[kk][1], qf[kk][2], qf[kk][3], b0, b1);
            }
        }

        // causal mask (diagonal tile only)
        if (kt == qt) {
            #pragma unroll
            for (int n = 0; n < 8; n++) {
                const int c = k0 + n * 8 + 2 * tg;
                if (c > t0)     sf[n][0] = -1e30f;
                if (c + 1 > t0) sf[n][1] = -1e30f;
                if (c > t1)     sf[n][2] = -1e30f;
                if (c + 1 > t1) sf[n][3] = -1e30f;
            }
        }

        // online softmax on fragments
        float rm0 = -1e30f, rm1 = -1e30f;
        #pragma unroll
        for (int n = 0; n < 8; n++) {
            rm0 = fmaxf(rm0, fmaxf(sf[n][0], sf[n][1]));
            rm1 = fmaxf(rm1, fmaxf(sf[n][2], sf[n][3]));
        }
        rm0 = red4max(rm0);
        rm1 = red4max(rm1);
        const float mn0 = fmaxf(m0, rm0), mn1 = fmaxf(m1, rm1);
        const float a0 = __expf(m0 - mn0), a1 = __expf(m1 - mn1);
        float rs0 = 0.0f, rs1 = 0.0f;
        #pragma unroll
        for (int n = 0; n < 8; n++) {
            const float p00 = __expf(sf[n][0] - mn0);
            const float p01 = __expf(sf[n][1] - mn0);
            const float p10 = __expf(sf[n][2] - mn1);
            const float p11 = __expf(sf[n][3] - mn1);
            rs0 += p00 + p01;
            rs1 += p10 + p11;
            *(uint2*)&Ps[(rr + g) * LQ + n * 8 + 2 * tg]     = make_uint2(f2tf(p00), f2tf(p01));
            *(uint2*)&Ps[(rr + g + 8) * LQ + n * 8 + 2 * tg] = make_uint2(f2tf(p10), f2tf(p11));
        }
        rs0 = red4sum(rs0);
        rs1 = red4sum(rs1);
        l0 = l0 * a0 + rs0;  m0 = mn0;
        l1 = l1 * a1 + rs1;  m1 = mn1;
        #pragma unroll
        for (int n = 0; n < 8; n++) {
            of[n][0] *= a0; of[n][1] *= a0;
            of[n][2] *= a1; of[n][3] *= a1;
        }
        __syncwarp();   // Ps rows are warp-private; only warp-level ordering needed

        // O += P * V
        #pragma unroll
        for (int kk = 0; kk < 8; kk++) {
            uint32_t pa0 = Ps[(rr + g) * LQ + kk * 8 + tg];
            uint32_t pa1 = Ps[(rr + g + 8) * LQ + kk * 8 + tg];
            uint32_t pa2 = Ps[(rr + g) * LQ + kk * 8 + tg + 4];
            uint32_t pa3 = Ps[(rr + g + 8) * LQ + kk * 8 + tg + 4];
            #pragma unroll
            for (int n = 0; n < 8; n++) {
                uint32_t b0 = Vs[(kk * 8 + tg) * LV + n * 8 + g];
                uint32_t b1 = Vs[(kk * 8 + tg + 4) * LV + n * 8 + g];
                mma8(of[n], pa0, pa1, pa2, pa3, b0, b1);
            }
        }
    }

    // normalize + store to [B*T, C]
    const float il0 = 1.0f / l0, il1 = 1.0f / l1;
    const int b = bh >> 4;
    const int h = bh & 15;
    #pragma unroll
    for (int n = 0; n < 8; n++) {
        const int d = h * 64 + n * 8 + 2 * tg;
        *(float2*)&Oatt[(size_t)(b * T_ + t0) * C_ + d] =
            make_float2(of[n][0] * il0, of[n][1] * il0);
        *(float2*)&Oatt[(size_t)(b * T_ + t1) * C_ + d] =
            make_float2(of[n][2] * il1, of[n][3] * il1);
    }
}

// ---------------------------------------------------------------------------
extern "C" void kernel_launch(void* const* d_in, const int* in_sizes, int n_in,
                              void* d_out, int out_size)
{
    const float* x     = (const float*)d_in[0];
    // d_in[1] = mask (causal, static; unused)
    const float* qkv_w = (const float*)d_in[2];
    const float* qkv_b = (const float*)d_in[3];
    const float* out_w = (const float*)d_in[4];
    const float* out_b = (const float*)d_in[5];
    float* out = (float*)d_out;

    float *qp, *kp, *vp, *ap;
    cudaGetSymbolAddress((void**)&qp, g_q);
    cudaGetSymbolAddress((void**)&kp, g_k);
    cudaGetSymbolAddress((void**)&vp, g_v);
    cudaGetSymbolAddress((void**)&ap, g_att);

    cudaFuncSetAttribute(attn_tf32,
                         cudaFuncAttributeMaxDynamicSharedMemorySize,
                         ATTN_BYTES);

    // 1) QKV projection
    dim3 g1(NQKV / 128, BT_ / 128);
    gemm_tf32<0><<<g1, 256>>>(x, qkv_w, qkv_b, nullptr, qp, kp, vp,
                              BT_, NQKV, C_);

    // 2) causal flash attention (tensor cores)
    dim3 g2(T_ / 64, B_ * H_);
    attn_tf32<<<g2, 128, ATTN_BYTES>>>(qp, kp, vp, ap);

    // 3) output projection
    dim3 g3(C_ / 128, BT_ / 128);
    gemm_tf32<1><<<g3, 256>>>(ap, out_w, out_b, out,
                              nullptr, nullptr, nullptr,
                              BT_, C_, C_);
}